// round 1
// baseline (speedup 1.0000x reference)
#include <cuda_runtime.h>

// Problem constants
#define Bn   4
#define Sn   1024
#define INn  6
#define Dn   512
#define Hn   8
#define Ln   4
#define Fn   2048
#define DKn  64
#define BSn  (Bn * Sn)   // 4096 tokens

// ---------------- scratch (static device globals; no allocation) ----------------
__device__ float gbuf_left [BSn * Dn];
__device__ float gbuf_right[BSn * Dn];
__device__ float gbuf_lc   [BSn * Dn];
__device__ float gbuf_rc   [BSn * Dn];
__device__ float gbuf_q    [BSn * Dn];
__device__ float gbuf_k    [BSn * Dn];
__device__ float gbuf_v    [BSn * Dn];
__device__ float gbuf_ctx  [BSn * Dn];
__device__ float gbuf_o    [BSn * Dn];
__device__ float gbuf_sc   [(long long)Bn * Hn * Sn * Sn]; // 32M floats = 128MB
__device__ float gbuf_ffh  [BSn * Fn];                      // 32MB
__device__ float gbuf_fused[Bn * 2 * Dn];

// ---------------- embedding: out = in @ W + b + pe ----------------
__global__ void embed_kernel(const float* __restrict__ in, const float* __restrict__ W,
                             const float* __restrict__ bias, const float* __restrict__ pe,
                             float* __restrict__ out)
{
    int idx = blockIdx.x * 256 + threadIdx.x;          // < BSn*Dn
    int d = idx & (Dn - 1);
    int t = idx >> 9;                                  // token index
    int s = t & (Sn - 1);
    float acc = bias[d] + pe[s * Dn + d];
#pragma unroll
    for (int i = 0; i < INn; i++)
        acc += in[t * INn + i] * W[i * Dn + d];
    out[idx] = acc;
}

// ---------------- generic tiled SGEMM ----------------
// C[z] = alpha * A[z] (@ B[z] or @ B[z]^T) + bias ; optional relu.
// Per-batch offsets: off = (z / Hdiv)*s?b + (z % Hdiv)*s?h.
// All dims assumed multiples of tile sizes (true for this problem).
#define BM 64
#define BN 64
#define BK 16

template <bool TRANSB, bool RELU>
__global__ __launch_bounds__(256)
void sgemm(const float* __restrict__ A, const float* __restrict__ Bm,
           const float* __restrict__ bias, float* __restrict__ C,
           int K, int lda, int ldb, int ldc, int Hdiv,
           long long sAb, long long sAh,
           long long sBb, long long sBh,
           long long sCb, long long sCh,
           float alpha)
{
    __shared__ float As[BK][BM];
    __shared__ float Bs[BK][BN];

    int z  = blockIdx.z;
    int zb = z / Hdiv, zh = z % Hdiv;
    A  += zb * sAb + zh * sAh;
    Bm += zb * sBb + zh * sBh;
    C  += zb * sCb + zh * sCh;

    int bm = blockIdx.y * BM;
    int bn = blockIdx.x * BN;
    int tid = threadIdx.x;
    int tx = tid & 15, ty = tid >> 4;

    float acc[4][4];
#pragma unroll
    for (int i = 0; i < 4; i++)
#pragma unroll
        for (int j = 0; j < 4; j++) acc[i][j] = 0.f;

    for (int k0 = 0; k0 < K; k0 += BK) {
        // A tile [BM][BK] -> As[kk][row]
#pragma unroll
        for (int i = tid; i < BM * BK; i += 256) {
            int r = i >> 4, c = i & 15;
            As[c][r] = A[(long long)(bm + r) * lda + (k0 + c)];
        }
        if (!TRANSB) {
#pragma unroll
            for (int i = tid; i < BK * BN; i += 256) {
                int r = i >> 6, c = i & 63;   // B[k0+r][bn+c]
                Bs[r][c] = Bm[(long long)(k0 + r) * ldb + (bn + c)];
            }
        } else {
#pragma unroll
            for (int i = tid; i < BN * BK; i += 256) {
                int r = i >> 4, c = i & 15;   // B[bn+r][k0+c], B stored [N,K]
                Bs[c][r] = Bm[(long long)(bn + r) * ldb + (k0 + c)];
            }
        }
        __syncthreads();

#pragma unroll
        for (int kk = 0; kk < BK; kk++) {
            float a[4], b[4];
#pragma unroll
            for (int i = 0; i < 4; i++) a[i] = As[kk][ty * 4 + i];
#pragma unroll
            for (int j = 0; j < 4; j++) b[j] = Bs[kk][tx * 4 + j];
#pragma unroll
            for (int i = 0; i < 4; i++)
#pragma unroll
                for (int j = 0; j < 4; j++)
                    acc[i][j] += a[i] * b[j];
        }
        __syncthreads();
    }

#pragma unroll
    for (int i = 0; i < 4; i++) {
        int row = bm + ty * 4 + i;
#pragma unroll
        for (int j = 0; j < 4; j++) {
            int col = bn + tx * 4 + j;
            float v = acc[i][j] * alpha + (bias ? bias[col] : 0.f);
            if (RELU) v = fmaxf(v, 0.f);
            C[(long long)row * ldc + col] = v;
        }
    }
}

// ---------------- row softmax over 1024 cols ----------------
__global__ void softmax_kernel(float* __restrict__ s)
{
    long long row = blockIdx.x;
    float* p = s + row * Sn;
    int t = threadIdx.x;                 // 256 threads, 4 elems each
    float v[4];
    float m = -1e30f;
#pragma unroll
    for (int i = 0; i < 4; i++) { v[i] = p[t + i * 256]; m = fmaxf(m, v[i]); }

    __shared__ float red[256];
    red[t] = m; __syncthreads();
#pragma unroll
    for (int o = 128; o > 0; o >>= 1) {
        if (t < o) red[t] = fmaxf(red[t], red[t + o]);
        __syncthreads();
    }
    m = red[0]; __syncthreads();

    float sum = 0.f;
#pragma unroll
    for (int i = 0; i < 4; i++) { v[i] = __expf(v[i] - m); sum += v[i]; }
    red[t] = sum; __syncthreads();
#pragma unroll
    for (int o = 128; o > 0; o >>= 1) {
        if (t < o) red[t] += red[t + o];
        __syncthreads();
    }
    float inv = 1.f / red[0];
#pragma unroll
    for (int i = 0; i < 4; i++) p[t + i * 256] = v[i] * inv;
}

// ---------------- add residual + layernorm (D=512) ----------------
__global__ void add_ln_kernel(const float* __restrict__ x, const float* __restrict__ r,
                              const float* __restrict__ g, const float* __restrict__ be,
                              float* __restrict__ out)
{
    long long row = blockIdx.x;
    const float* xp = x + row * Dn;
    const float* rp = r + row * Dn;
    int t = threadIdx.x;                 // 128 threads, 4 elems each
    float v[4]; float s = 0.f, s2 = 0.f;
#pragma unroll
    for (int i = 0; i < 4; i++) {
        int c = t + i * 128;
        v[i] = xp[c] + rp[c];
        s += v[i]; s2 += v[i] * v[i];
    }
    __shared__ float rs[128], rs2[128];
    rs[t] = s; rs2[t] = s2; __syncthreads();
#pragma unroll
    for (int o = 64; o > 0; o >>= 1) {
        if (t < o) { rs[t] += rs[t + o]; rs2[t] += rs2[t + o]; }
        __syncthreads();
    }
    float mean = rs[0] * (1.f / Dn);
    float var  = rs2[0] * (1.f / Dn) - mean * mean;
    float rstd = rsqrtf(var + 1e-5f);
    float* op = out + row * Dn;
#pragma unroll
    for (int i = 0; i < 4; i++) {
        int c = t + i * 128;
        op[c] = (v[i] - mean) * rstd * g[c] + be[c];
    }
}

// ---------------- mean-pool over sequence ----------------
__global__ void pool_kernel(const float* __restrict__ left, const float* __restrict__ right,
                            float* __restrict__ fused)
{
    int idx = blockIdx.x * 256 + threadIdx.x;     // < Bn*2*Dn
    int b = idx >> 10;
    int c = idx & 1023;
    const float* src = (c < Dn) ? (left  + (long long)b * Sn * Dn + c)
                                : (right + (long long)b * Sn * Dn + (c - Dn));
    float s = 0.f;
    for (int t = 0; t < Sn; t++) s += src[(long long)t * Dn];
    fused[idx] = s * (1.f / Sn);
}

// ---------------- classifier head: relu(fused@w1+b1)@w2+b2 ----------------
__global__ void head_kernel(const float* __restrict__ fused,
                            const float* __restrict__ w1, const float* __restrict__ b1,
                            const float* __restrict__ w2, const float* __restrict__ b2,
                            float* __restrict__ out)
{
    __shared__ float sf[2 * Dn];
    int b = blockIdx.x, t = threadIdx.x;          // 512 threads
    sf[t]       = fused[b * 2 * Dn + t];
    sf[t + Dn]  = fused[b * 2 * Dn + t + Dn];
    __syncthreads();
    float h = b1[t];
    for (int k = 0; k < 2 * Dn; k++)
        h += sf[k] * w1[k * Dn + t];
    h = fmaxf(h, 0.f);
    __shared__ float r0[512], r1[512];
    r0[t] = h * w2[t * 2 + 0];
    r1[t] = h * w2[t * 2 + 1];
    __syncthreads();
#pragma unroll
    for (int o = 256; o > 0; o >>= 1) {
        if (t < o) { r0[t] += r0[t + o]; r1[t] += r1[t + o]; }
        __syncthreads();
    }
    if (t == 0) {
        out[b * 2 + 0] = r0[0] + b2[0];
        out[b * 2 + 1] = r1[0] + b2[1];
    }
}

// ---------------- host-side helpers ----------------
static inline void gemm_plain(const float* A, const float* B, const float* bias, float* C,
                              int M, int N, int K, bool relu)
{
    dim3 g(N / BN, M / BM, 1);
    if (relu)
        sgemm<false, true ><<<g, 256>>>(A, B, bias, C, K, K, N, N, 1, 0, 0, 0, 0, 0, 0, 1.f);
    else
        sgemm<false, false><<<g, 256>>>(A, B, bias, C, K, K, N, N, 1, 0, 0, 0, 0, 0, 0, 1.f);
}

static void run_mha(const float* qin, const float* kin,
                    const float* w, const float* bb,
                    const float* g, const float* be,
                    float* q, float* k, float* v, float* ctx, float* o, float* sc,
                    float* out)
{
    gemm_plain(qin, w + 0 * Dn * Dn, bb + 0 * Dn, q, BSn, Dn, Dn, false);
    gemm_plain(kin, w + 1 * Dn * Dn, bb + 1 * Dn, k, BSn, Dn, Dn, false);
    gemm_plain(kin, w + 2 * Dn * Dn, bb + 2 * Dn, v, BSn, Dn, Dn, false);

    { // scores = Q @ K^T * 1/sqrt(dk), batched over (b,h)
        dim3 gr(Sn / BN, Sn / BM, Bn * Hn);
        sgemm<true, false><<<gr, 256>>>(q, k, nullptr, sc, DKn,
            Dn, Dn, Sn, Hn,
            (long long)Sn * Dn, DKn,
            (long long)Sn * Dn, DKn,
            (long long)Hn * Sn * Sn, (long long)Sn * Sn,
            0.125f);
    }
    softmax_kernel<<<Bn * Hn * Sn, 256>>>(sc);
    { // ctx = P @ V, batched over (b,h); written straight into token layout
        dim3 gr(DKn / BN, Sn / BM, Bn * Hn);
        sgemm<false, false><<<gr, 256>>>(sc, v, nullptr, ctx, Sn,
            Sn, Dn, Dn, Hn,
            (long long)Hn * Sn * Sn, (long long)Sn * Sn,
            (long long)Sn * Dn, DKn,
            (long long)Sn * Dn, DKn,
            1.f);
    }
    gemm_plain(ctx, w + 3 * Dn * Dn, bb + 3 * Dn, o, BSn, Dn, Dn, false);
    add_ln_kernel<<<BSn, 128>>>(o, qin, g, be, out);
}

static void run_ffn(float* x,
                    const float* w1, const float* b1,
                    const float* w2, const float* b2,
                    const float* g, const float* be,
                    float* hbuf, float* obuf)
{
    gemm_plain(x, w1, b1, hbuf, BSn, Fn, Dn, true);
    gemm_plain(hbuf, w2, b2, obuf, BSn, Dn, Fn, false);
    add_ln_kernel<<<BSn, 128>>>(obuf, x, g, be, x);   // in-place over residual (row-local, safe)
}

extern "C" void kernel_launch(void* const* d_in, const int* in_sizes, int n_in,
                              void* d_out, int out_size)
{
    const float* left_wrist  = (const float*)d_in[0];
    const float* right_wrist = (const float*)d_in[1];
    const float* Wl = (const float*)d_in[2];
    const float* bl = (const float*)d_in[3];
    const float* Wr = (const float*)d_in[4];
    const float* br = (const float*)d_in[5];
    const float* pe = (const float*)d_in[6];
    const float* mha_w    = (const float*)d_in[7];
    const float* mha_b    = (const float*)d_in[8];
    const float* mha_ln_g = (const float*)d_in[9];
    const float* mha_ln_b = (const float*)d_in[10];
    const float* ff_w1    = (const float*)d_in[11];
    const float* ff_b1    = (const float*)d_in[12];
    const float* ff_w2    = (const float*)d_in[13];
    const float* ff_b2    = (const float*)d_in[14];
    const float* ff_ln_g  = (const float*)d_in[15];
    const float* ff_ln_b  = (const float*)d_in[16];
    const float* h1_w1 = (const float*)d_in[17];
    const float* h1_b1 = (const float*)d_in[18];
    const float* h1_w2 = (const float*)d_in[19];
    const float* h1_b2 = (const float*)d_in[20];
    const float* h2_w1 = (const float*)d_in[21];
    const float* h2_b1 = (const float*)d_in[22];
    const float* h2_w2 = (const float*)d_in[23];
    const float* h2_b2 = (const float*)d_in[24];
    float* out = (float*)d_out;

    float *pLeft, *pRight, *pLc, *pRc, *pQ, *pK, *pV, *pCtx, *pO, *pSc, *pFfh, *pFused;
    cudaGetSymbolAddress((void**)&pLeft,  gbuf_left);
    cudaGetSymbolAddress((void**)&pRight, gbuf_right);
    cudaGetSymbolAddress((void**)&pLc,    gbuf_lc);
    cudaGetSymbolAddress((void**)&pRc,    gbuf_rc);
    cudaGetSymbolAddress((void**)&pQ,     gbuf_q);
    cudaGetSymbolAddress((void**)&pK,     gbuf_k);
    cudaGetSymbolAddress((void**)&pV,     gbuf_v);
    cudaGetSymbolAddress((void**)&pCtx,   gbuf_ctx);
    cudaGetSymbolAddress((void**)&pO,     gbuf_o);
    cudaGetSymbolAddress((void**)&pSc,    gbuf_sc);
    cudaGetSymbolAddress((void**)&pFfh,   gbuf_ffh);
    cudaGetSymbolAddress((void**)&pFused, gbuf_fused);

    embed_kernel<<<(BSn * Dn) / 256, 256>>>(left_wrist,  Wl, bl, pe, pLeft);
    embed_kernel<<<(BSn * Dn) / 256, 256>>>(right_wrist, Wr, br, pe, pRight);

    for (int l = 0; l < Ln; l++) {
        const float* w_base  = mha_w    + (long long)l * 4 * 4 * Dn * Dn;
        const float* b_base  = mha_b    + (long long)l * 4 * 4 * Dn;
        const float* lg_base = mha_ln_g + (long long)l * 4 * Dn;
        const float* lb_base = mha_ln_b + (long long)l * 4 * Dn;

        // cross attention: lc = MHA(left, right, right); rc = MHA(right, left, left)
        run_mha(pLeft,  pRight, w_base + 0 * 4 * Dn * Dn, b_base + 0 * 4 * Dn,
                lg_base + 0 * Dn, lb_base + 0 * Dn, pQ, pK, pV, pCtx, pO, pSc, pLc);
        run_mha(pRight, pLeft,  w_base + 1 * 4 * Dn * Dn, b_base + 1 * 4 * Dn,
                lg_base + 1 * Dn, lb_base + 1 * Dn, pQ, pK, pV, pCtx, pO, pSc, pRc);
        // self attention: ls -> pLeft, rs -> pRight
        run_mha(pLc, pLc, w_base + 2 * 4 * Dn * Dn, b_base + 2 * 4 * Dn,
                lg_base + 2 * Dn, lb_base + 2 * Dn, pQ, pK, pV, pCtx, pO, pSc, pLeft);
        run_mha(pRc, pRc, w_base + 3 * 4 * Dn * Dn, b_base + 3 * 4 * Dn,
                lg_base + 3 * Dn, lb_base + 3 * Dn, pQ, pK, pV, pCtx, pO, pSc, pRight);

        // FFNs (in place on pLeft / pRight)
        run_ffn(pLeft,
                ff_w1 + ((long long)l * 2 + 0) * Dn * Fn, ff_b1 + ((long long)l * 2 + 0) * Fn,
                ff_w2 + ((long long)l * 2 + 0) * Fn * Dn, ff_b2 + ((long long)l * 2 + 0) * Dn,
                ff_ln_g + ((long long)l * 2 + 0) * Dn, ff_ln_b + ((long long)l * 2 + 0) * Dn,
                pFfh, pO);
        run_ffn(pRight,
                ff_w1 + ((long long)l * 2 + 1) * Dn * Fn, ff_b1 + ((long long)l * 2 + 1) * Fn,
                ff_w2 + ((long long)l * 2 + 1) * Fn * Dn, ff_b2 + ((long long)l * 2 + 1) * Dn,
                ff_ln_g + ((long long)l * 2 + 1) * Dn, ff_ln_b + ((long long)l * 2 + 1) * Dn,
                pFfh, pO);
    }

    pool_kernel<<<(Bn * 2 * Dn) / 256, 256>>>(pLeft, pRight, pFused);
    head_kernel<<<Bn, 512>>>(pFused, h1_w1, h1_b1, h1_w2, h1_b2, out);
    head_kernel<<<Bn, 512>>>(pFused, h2_w1, h2_b1, h2_w2, h2_b2, out + Bn * 2);
}

// round 2
// speedup vs baseline: 2.7508x; 2.7508x over previous
#include <cuda_runtime.h>
#include <cstdint>

// Problem constants
#define Bn   4
#define Sn   1024
#define INn  6
#define Dn   512
#define Hn   8
#define Ln   4
#define Fn   2048
#define DKn  64
#define BSn  (Bn * Sn)   // 4096 tokens

// ---------------- scratch (static device globals; no allocation) ----------------
__device__ float gbuf_left [BSn * Dn];
__device__ float gbuf_right[BSn * Dn];
__device__ float gbuf_lc   [BSn * Dn];
__device__ float gbuf_rc   [BSn * Dn];
__device__ float gbuf_q    [BSn * Dn];
__device__ float gbuf_k    [BSn * Dn];
__device__ float gbuf_v    [BSn * Dn];
__device__ float gbuf_ctx  [BSn * Dn];
__device__ float gbuf_o    [BSn * Dn];
__device__ float gbuf_sc   [(long long)Bn * Hn * Sn * Sn]; // 128MB
__device__ float gbuf_ffh  [BSn * Fn];                      // 32MB
__device__ float gbuf_fused[Bn * 2 * Dn];

// ---------------- embedding: out = in @ W + b + pe ----------------
__global__ void embed_kernel(const float* __restrict__ in, const float* __restrict__ W,
                             const float* __restrict__ bias, const float* __restrict__ pe,
                             float* __restrict__ out)
{
    int idx = blockIdx.x * 256 + threadIdx.x;
    int d = idx & (Dn - 1);
    int t = idx >> 9;
    int s = t & (Sn - 1);
    float acc = bias[d] + pe[s * Dn + d];
#pragma unroll
    for (int i = 0; i < INn; i++)
        acc += in[t * INn + i] * W[i * Dn + d];
    out[idx] = acc;
}

// ---------------- TF32 tensor-core GEMM ----------------
// C[z] = alpha * A[z] (@ B[z] or @ B[z]^T) + bias ; optional relu.
// Tiles: 128(M) x 64(N) x 16(K). 256 threads = 8 warps (4 M x 2 N).
// Warp tile 32x32 = 2x4 m16n8k8 tf32 mma atoms.
#define BM 128
#define BN 64
#define BK 16

__device__ __forceinline__ float to_tf32(float x) {
    float r;
    asm("cvt.rna.tf32.f32 %0, %1;" : "=f"(r) : "f"(x));
    return r;
}

__device__ __forceinline__ void mma_tf32(float* d, const uint32_t* a, const uint32_t* b) {
    asm volatile(
        "mma.sync.aligned.m16n8k8.row.col.f32.tf32.tf32.f32 "
        "{%0,%1,%2,%3}, {%4,%5,%6,%7}, {%8,%9}, {%0,%1,%2,%3};\n"
        : "+f"(d[0]), "+f"(d[1]), "+f"(d[2]), "+f"(d[3])
        : "r"(a[0]), "r"(a[1]), "r"(a[2]), "r"(a[3]),
          "r"(b[0]), "r"(b[1]));
}

// As[2][BM][20] : fragment load a = As[m][kk+ctid]; pad 20 -> conflict-free (20*g mod 32 distinct).
// Bs[2][BK][72] : fragment load b = Bs[kk+ctid][n]; 72 mod 32 = 8 -> ctid*8+gid distinct.
#define APAD 20
#define BPAD 72

template <bool TRANSB, bool RELU>
__global__ __launch_bounds__(256)
void tgemm(const float* __restrict__ A, const float* __restrict__ Bm,
           const float* __restrict__ bias, float* __restrict__ C,
           int K, int lda, int ldb, int ldc, int Hdiv,
           long long sAb, long long sAh,
           long long sBb, long long sBh,
           long long sCb, long long sCh,
           float alpha)
{
    __shared__ float As[2][BM][APAD];
    __shared__ float Bs[2][BK][BPAD];

    int z  = blockIdx.z;
    int zb = z / Hdiv, zh = z % Hdiv;
    A  += zb * sAb + zh * sAh;
    Bm += zb * sBb + zh * sBh;
    C  += zb * sCb + zh * sCh;

    const int bm = blockIdx.y * BM;
    const int bn = blockIdx.x * BN;
    const int tid = threadIdx.x;
    const int lane = tid & 31;
    const int warp = tid >> 5;
    const int wm = (warp >> 1) * 32;
    const int wn = (warp & 1) * 32;
    const int gid = lane >> 2;
    const int ctid = lane & 3;

    // A load mapping: 512 float4 slots, 2 per thread
    const int a_kc4 = tid & 3;          // float4 index along K
    const int a_row0 = tid >> 2;        // rows 0..63 (v=0), +64 (v=1)
    // B load mapping
    const int b_nc4 = tid & 15;         // non-trans: float4 along N
    const int b_krow = tid >> 4;
    const int bt_kc4 = tid & 3;         // trans: float4 along K
    const int bt_n = tid >> 2;

    float acc[2][4][4];
#pragma unroll
    for (int i = 0; i < 2; i++)
#pragma unroll
        for (int j = 0; j < 4; j++)
#pragma unroll
            for (int q = 0; q < 4; q++) acc[i][j][q] = 0.f;

    const int NT = K / BK;
    float4 ra[2], rb;

    // ---- load tile 0 ----
#pragma unroll
    for (int v = 0; v < 2; v++)
        ra[v] = *(const float4*)&A[(long long)(bm + a_row0 + v * 64) * lda + a_kc4 * 4];
    if (!TRANSB)
        rb = *(const float4*)&Bm[(long long)(b_krow) * ldb + bn + b_nc4 * 4];
    else
        rb = *(const float4*)&Bm[(long long)(bn + bt_n) * ldb + bt_kc4 * 4];

    // ---- store tile 0 ----
#pragma unroll
    for (int v = 0; v < 2; v++) {
        float4 t = ra[v];
        t.x = to_tf32(t.x); t.y = to_tf32(t.y); t.z = to_tf32(t.z); t.w = to_tf32(t.w);
        *(float4*)&As[0][a_row0 + v * 64][a_kc4 * 4] = t;
    }
    if (!TRANSB) {
        float4 t = rb;
        t.x = to_tf32(t.x); t.y = to_tf32(t.y); t.z = to_tf32(t.z); t.w = to_tf32(t.w);
        *(float4*)&Bs[0][b_krow][b_nc4 * 4] = t;
    } else {
        Bs[0][bt_kc4 * 4 + 0][bt_n] = to_tf32(rb.x);
        Bs[0][bt_kc4 * 4 + 1][bt_n] = to_tf32(rb.y);
        Bs[0][bt_kc4 * 4 + 2][bt_n] = to_tf32(rb.z);
        Bs[0][bt_kc4 * 4 + 3][bt_n] = to_tf32(rb.w);
    }
    __syncthreads();

    for (int t = 0; t < NT; t++) {
        // prefetch next tile into regs
        if (t + 1 < NT) {
            int k0 = (t + 1) * BK;
#pragma unroll
            for (int v = 0; v < 2; v++)
                ra[v] = *(const float4*)&A[(long long)(bm + a_row0 + v * 64) * lda + k0 + a_kc4 * 4];
            if (!TRANSB)
                rb = *(const float4*)&Bm[(long long)(k0 + b_krow) * ldb + bn + b_nc4 * 4];
            else
                rb = *(const float4*)&Bm[(long long)(bn + bt_n) * ldb + k0 + bt_kc4 * 4];
        }

        // compute from buffer t&1
        const int buf = t & 1;
#pragma unroll
        for (int kk = 0; kk < BK; kk += 8) {
            uint32_t afr[2][4];
#pragma unroll
            for (int i = 0; i < 2; i++) {
                int m = wm + i * 16;
                afr[i][0] = *(const uint32_t*)&As[buf][m + gid][kk + ctid];
                afr[i][1] = *(const uint32_t*)&As[buf][m + gid + 8][kk + ctid];
                afr[i][2] = *(const uint32_t*)&As[buf][m + gid][kk + ctid + 4];
                afr[i][3] = *(const uint32_t*)&As[buf][m + gid + 8][kk + ctid + 4];
            }
            uint32_t bfr[4][2];
#pragma unroll
            for (int j = 0; j < 4; j++) {
                int n = wn + j * 8 + gid;
                bfr[j][0] = *(const uint32_t*)&Bs[buf][kk + ctid][n];
                bfr[j][1] = *(const uint32_t*)&Bs[buf][kk + ctid + 4][n];
            }
#pragma unroll
            for (int i = 0; i < 2; i++)
#pragma unroll
                for (int j = 0; j < 4; j++)
                    mma_tf32(acc[i][j], afr[i], bfr[j]);
        }

        // store prefetched tile into the other buffer
        if (t + 1 < NT) {
            const int nbuf = (t + 1) & 1;
#pragma unroll
            for (int v = 0; v < 2; v++) {
                float4 tt = ra[v];
                tt.x = to_tf32(tt.x); tt.y = to_tf32(tt.y); tt.z = to_tf32(tt.z); tt.w = to_tf32(tt.w);
                *(float4*)&As[nbuf][a_row0 + v * 64][a_kc4 * 4] = tt;
            }
            if (!TRANSB) {
                float4 tt = rb;
                tt.x = to_tf32(tt.x); tt.y = to_tf32(tt.y); tt.z = to_tf32(tt.z); tt.w = to_tf32(tt.w);
                *(float4*)&Bs[nbuf][b_krow][b_nc4 * 4] = tt;
            } else {
                Bs[nbuf][bt_kc4 * 4 + 0][bt_n] = to_tf32(rb.x);
                Bs[nbuf][bt_kc4 * 4 + 1][bt_n] = to_tf32(rb.y);
                Bs[nbuf][bt_kc4 * 4 + 2][bt_n] = to_tf32(rb.z);
                Bs[nbuf][bt_kc4 * 4 + 3][bt_n] = to_tf32(rb.w);
            }
        }
        __syncthreads();
    }

    // ---- epilogue ----
#pragma unroll
    for (int i = 0; i < 2; i++) {
        int row0 = bm + wm + i * 16 + gid;
        int row1 = row0 + 8;
#pragma unroll
        for (int j = 0; j < 4; j++) {
            int col = bn + wn + j * 8 + 2 * ctid;
            float bv0 = bias ? bias[col] : 0.f;
            float bv1 = bias ? bias[col + 1] : 0.f;
            float2 o0, o1;
            o0.x = acc[i][j][0] * alpha + bv0;
            o0.y = acc[i][j][1] * alpha + bv1;
            o1.x = acc[i][j][2] * alpha + bv0;
            o1.y = acc[i][j][3] * alpha + bv1;
            if (RELU) {
                o0.x = fmaxf(o0.x, 0.f); o0.y = fmaxf(o0.y, 0.f);
                o1.x = fmaxf(o1.x, 0.f); o1.y = fmaxf(o1.y, 0.f);
            }
            *(float2*)&C[(long long)row0 * ldc + col] = o0;
            *(float2*)&C[(long long)row1 * ldc + col] = o1;
        }
    }
}

// ---------------- row softmax over 1024 cols ----------------
__global__ void softmax_kernel(float* __restrict__ s)
{
    long long row = blockIdx.x;
    float* p = s + row * Sn;
    int t = threadIdx.x;
    float v[4];
    float m = -1e30f;
#pragma unroll
    for (int i = 0; i < 4; i++) { v[i] = p[t + i * 256]; m = fmaxf(m, v[i]); }

    __shared__ float red[256];
    red[t] = m; __syncthreads();
#pragma unroll
    for (int o = 128; o > 0; o >>= 1) {
        if (t < o) red[t] = fmaxf(red[t], red[t + o]);
        __syncthreads();
    }
    m = red[0]; __syncthreads();

    float sum = 0.f;
#pragma unroll
    for (int i = 0; i < 4; i++) { v[i] = __expf(v[i] - m); sum += v[i]; }
    red[t] = sum; __syncthreads();
#pragma unroll
    for (int o = 128; o > 0; o >>= 1) {
        if (t < o) red[t] += red[t + o];
        __syncthreads();
    }
    float inv = 1.f / red[0];
#pragma unroll
    for (int i = 0; i < 4; i++) p[t + i * 256] = v[i] * inv;
}

// ---------------- add residual + layernorm (D=512) ----------------
__global__ void add_ln_kernel(const float* __restrict__ x, const float* __restrict__ r,
                              const float* __restrict__ g, const float* __restrict__ be,
                              float* __restrict__ out)
{
    long long row = blockIdx.x;
    const float* xp = x + row * Dn;
    const float* rp = r + row * Dn;
    int t = threadIdx.x;
    float v[4]; float s = 0.f, s2 = 0.f;
#pragma unroll
    for (int i = 0; i < 4; i++) {
        int c = t + i * 128;
        v[i] = xp[c] + rp[c];
        s += v[i]; s2 += v[i] * v[i];
    }
    __shared__ float rs[128], rs2[128];
    rs[t] = s; rs2[t] = s2; __syncthreads();
#pragma unroll
    for (int o = 64; o > 0; o >>= 1) {
        if (t < o) { rs[t] += rs[t + o]; rs2[t] += rs2[t + o]; }
        __syncthreads();
    }
    float mean = rs[0] * (1.f / Dn);
    float var  = rs2[0] * (1.f / Dn) - mean * mean;
    float rstd = rsqrtf(var + 1e-5f);
    float* op = out + row * Dn;
#pragma unroll
    for (int i = 0; i < 4; i++) {
        int c = t + i * 128;
        op[c] = (v[i] - mean) * rstd * g[c] + be[c];
    }
}

// ---------------- mean-pool over sequence ----------------
__global__ void pool_kernel(const float* __restrict__ left, const float* __restrict__ right,
                            float* __restrict__ fused)
{
    int idx = blockIdx.x * 256 + threadIdx.x;
    int b = idx >> 10;
    int c = idx & 1023;
    const float* src = (c < Dn) ? (left  + (long long)b * Sn * Dn + c)
                                : (right + (long long)b * Sn * Dn + (c - Dn));
    float s = 0.f;
    for (int t = 0; t < Sn; t++) s += src[(long long)t * Dn];
    fused[idx] = s * (1.f / Sn);
}

// ---------------- classifier head ----------------
__global__ void head_kernel(const float* __restrict__ fused,
                            const float* __restrict__ w1, const float* __restrict__ b1,
                            const float* __restrict__ w2, const float* __restrict__ b2,
                            float* __restrict__ out)
{
    __shared__ float sf[2 * Dn];
    int b = blockIdx.x, t = threadIdx.x;
    sf[t]       = fused[b * 2 * Dn + t];
    sf[t + Dn]  = fused[b * 2 * Dn + t + Dn];
    __syncthreads();
    float h = b1[t];
    for (int k = 0; k < 2 * Dn; k++)
        h += sf[k] * w1[k * Dn + t];
    h = fmaxf(h, 0.f);
    __shared__ float r0[512], r1[512];
    r0[t] = h * w2[t * 2 + 0];
    r1[t] = h * w2[t * 2 + 1];
    __syncthreads();
#pragma unroll
    for (int o = 256; o > 0; o >>= 1) {
        if (t < o) { r0[t] += r0[t + o]; r1[t] += r1[t + o]; }
        __syncthreads();
    }
    if (t == 0) {
        out[b * 2 + 0] = r0[0] + b2[0];
        out[b * 2 + 1] = r1[0] + b2[1];
    }
}

// ---------------- host-side helpers ----------------
static inline void gemm_plain(const float* A, const float* B, const float* bias, float* C,
                              int M, int N, int K, bool relu)
{
    dim3 g(N / BN, M / BM, 1);
    if (relu)
        tgemm<false, true ><<<g, 256>>>(A, B, bias, C, K, K, N, N, 1, 0, 0, 0, 0, 0, 0, 1.f);
    else
        tgemm<false, false><<<g, 256>>>(A, B, bias, C, K, K, N, N, 1, 0, 0, 0, 0, 0, 0, 1.f);
}

static void run_mha(const float* qin, const float* kin,
                    const float* w, const float* bb,
                    const float* g, const float* be,
                    float* q, float* k, float* v, float* ctx, float* o, float* sc,
                    float* out)
{
    gemm_plain(qin, w + 0 * Dn * Dn, bb + 0 * Dn, q, BSn, Dn, Dn, false);
    gemm_plain(kin, w + 1 * Dn * Dn, bb + 1 * Dn, k, BSn, Dn, Dn, false);
    gemm_plain(kin, w + 2 * Dn * Dn, bb + 2 * Dn, v, BSn, Dn, Dn, false);

    { // scores = Q @ K^T * 1/sqrt(dk), batched over (b,h)
        dim3 gr(Sn / BN, Sn / BM, Bn * Hn);
        tgemm<true, false><<<gr, 256>>>(q, k, nullptr, sc, DKn,
            Dn, Dn, Sn, Hn,
            (long long)Sn * Dn, DKn,
            (long long)Sn * Dn, DKn,
            (long long)Hn * Sn * Sn, (long long)Sn * Sn,
            0.125f);
    }
    softmax_kernel<<<Bn * Hn * Sn, 256>>>(sc);
    { // ctx = P @ V, batched over (b,h)
        dim3 gr(DKn / BN, Sn / BM, Bn * Hn);
        tgemm<false, false><<<gr, 256>>>(sc, v, nullptr, ctx, Sn,
            Sn, Dn, Dn, Hn,
            (long long)Hn * Sn * Sn, (long long)Sn * Sn,
            (long long)Sn * Dn, DKn,
            (long long)Sn * Dn, DKn,
            1.f);
    }
    gemm_plain(ctx, w + 3 * Dn * Dn, bb + 3 * Dn, o, BSn, Dn, Dn, false);
    add_ln_kernel<<<BSn, 128>>>(o, qin, g, be, out);
}

static void run_ffn(float* x,
                    const float* w1, const float* b1,
                    const float* w2, const float* b2,
                    const float* g, const float* be,
                    float* hbuf, float* obuf)
{
    gemm_plain(x, w1, b1, hbuf, BSn, Fn, Dn, true);
    gemm_plain(hbuf, w2, b2, obuf, BSn, Dn, Fn, false);
    add_ln_kernel<<<BSn, 128>>>(obuf, x, g, be, x);
}

extern "C" void kernel_launch(void* const* d_in, const int* in_sizes, int n_in,
                              void* d_out, int out_size)
{
    const float* left_wrist  = (const float*)d_in[0];
    const float* right_wrist = (const float*)d_in[1];
    const float* Wl = (const float*)d_in[2];
    const float* bl = (const float*)d_in[3];
    const float* Wr = (const float*)d_in[4];
    const float* br = (const float*)d_in[5];
    const float* pe = (const float*)d_in[6];
    const float* mha_w    = (const float*)d_in[7];
    const float* mha_b    = (const float*)d_in[8];
    const float* mha_ln_g = (const float*)d_in[9];
    const float* mha_ln_b = (const float*)d_in[10];
    const float* ff_w1    = (const float*)d_in[11];
    const float* ff_b1    = (const float*)d_in[12];
    const float* ff_w2    = (const float*)d_in[13];
    const float* ff_b2    = (const float*)d_in[14];
    const float* ff_ln_g  = (const float*)d_in[15];
    const float* ff_ln_b  = (const float*)d_in[16];
    const float* h1_w1 = (const float*)d_in[17];
    const float* h1_b1 = (const float*)d_in[18];
    const float* h1_w2 = (const float*)d_in[19];
    const float* h1_b2 = (const float*)d_in[20];
    const float* h2_w1 = (const float*)d_in[21];
    const float* h2_b1 = (const float*)d_in[22];
    const float* h2_w2 = (const float*)d_in[23];
    const float* h2_b2 = (const float*)d_in[24];
    float* out = (float*)d_out;

    float *pLeft, *pRight, *pLc, *pRc, *pQ, *pK, *pV, *pCtx, *pO, *pSc, *pFfh, *pFused;
    cudaGetSymbolAddress((void**)&pLeft,  gbuf_left);
    cudaGetSymbolAddress((void**)&pRight, gbuf_right);
    cudaGetSymbolAddress((void**)&pLc,    gbuf_lc);
    cudaGetSymbolAddress((void**)&pRc,    gbuf_rc);
    cudaGetSymbolAddress((void**)&pQ,     gbuf_q);
    cudaGetSymbolAddress((void**)&pK,     gbuf_k);
    cudaGetSymbolAddress((void**)&pV,     gbuf_v);
    cudaGetSymbolAddress((void**)&pCtx,   gbuf_ctx);
    cudaGetSymbolAddress((void**)&pO,     gbuf_o);
    cudaGetSymbolAddress((void**)&pSc,    gbuf_sc);
    cudaGetSymbolAddress((void**)&pFfh,   gbuf_ffh);
    cudaGetSymbolAddress((void**)&pFused, gbuf_fused);

    embed_kernel<<<(BSn * Dn) / 256, 256>>>(left_wrist,  Wl, bl, pe, pLeft);
    embed_kernel<<<(BSn * Dn) / 256, 256>>>(right_wrist, Wr, br, pe, pRight);

    for (int l = 0; l < Ln; l++) {
        const float* w_base  = mha_w    + (long long)l * 4 * 4 * Dn * Dn;
        const float* b_base  = mha_b    + (long long)l * 4 * 4 * Dn;
        const float* lg_base = mha_ln_g + (long long)l * 4 * Dn;
        const float* lb_base = mha_ln_b + (long long)l * 4 * Dn;

        run_mha(pLeft,  pRight, w_base + 0 * 4 * Dn * Dn, b_base + 0 * 4 * Dn,
                lg_base + 0 * Dn, lb_base + 0 * Dn, pQ, pK, pV, pCtx, pO, pSc, pLc);
        run_mha(pRight, pLeft,  w_base + 1 * 4 * Dn * Dn, b_base + 1 * 4 * Dn,
                lg_base + 1 * Dn, lb_base + 1 * Dn, pQ, pK, pV, pCtx, pO, pSc, pRc);
        run_mha(pLc, pLc, w_base + 2 * 4 * Dn * Dn, b_base + 2 * 4 * Dn,
                lg_base + 2 * Dn, lb_base + 2 * Dn, pQ, pK, pV, pCtx, pO, pSc, pLeft);
        run_mha(pRc, pRc, w_base + 3 * 4 * Dn * Dn, b_base + 3 * 4 * Dn,
                lg_base + 3 * Dn, lb_base + 3 * Dn, pQ, pK, pV, pCtx, pO, pSc, pRight);

        run_ffn(pLeft,
                ff_w1 + ((long long)l * 2 + 0) * Dn * Fn, ff_b1 + ((long long)l * 2 + 0) * Fn,
                ff_w2 + ((long long)l * 2 + 0) * Fn * Dn, ff_b2 + ((long long)l * 2 + 0) * Dn,
                ff_ln_g + ((long long)l * 2 + 0) * Dn, ff_ln_b + ((long long)l * 2 + 0) * Dn,
                pFfh, pO);
        run_ffn(pRight,
                ff_w1 + ((long long)l * 2 + 1) * Dn * Fn, ff_b1 + ((long long)l * 2 + 1) * Fn,
                ff_w2 + ((long long)l * 2 + 1) * Fn * Dn, ff_b2 + ((long long)l * 2 + 1) * Dn,
                ff_ln_g + ((long long)l * 2 + 1) * Dn, ff_ln_b + ((long long)l * 2 + 1) * Dn,
                pFfh, pO);
    }

    pool_kernel<<<(Bn * 2 * Dn) / 256, 256>>>(pLeft, pRight, pFused);
    head_kernel<<<Bn, 512>>>(pFused, h1_w1, h1_b1, h1_w2, h1_b2, out);
    head_kernel<<<Bn, 512>>>(pFused, h2_w1, h2_b1, h2_w2, h2_b2, out + Bn * 2);
}

// round 3
// speedup vs baseline: 4.2660x; 1.5508x over previous
#include <cuda_runtime.h>
#include <cstdint>

// Problem constants
#define Bn   4
#define Sn   1024
#define INn  6
#define Dn   512
#define Hn   8
#define Ln   4
#define Fn   2048
#define DKn  64
#define BSn  (Bn * Sn)   // 4096 tokens
#define RR   ((long long)BSn * Dn)

// ---------------- scratch ----------------
__device__ float gbuf_x  [2 * BSn * Dn];   // left | right
__device__ float gbuf_c  [2 * BSn * Dn];   // lc | rc
__device__ float gbuf_qkv[6 * BSn * Dn];   // [blk][q/k/v][token][D]
__device__ float gbuf_ctx[2 * BSn * Dn];
__device__ float gbuf_o  [2 * BSn * Dn];
__device__ float gbuf_ffh[2 * BSn * Fn];
__device__ float gbuf_fused[Bn * 2 * Dn];

__device__ __forceinline__ float to_tf32(float x) {
    float r;
    asm("cvt.rna.tf32.f32 %0, %1;" : "=f"(r) : "f"(x));
    return r;
}

__device__ __forceinline__ void mma_tf32(float* d, const uint32_t* a, const uint32_t* b) {
    asm volatile(
        "mma.sync.aligned.m16n8k8.row.col.f32.tf32.tf32.f32 "
        "{%0,%1,%2,%3}, {%4,%5,%6,%7}, {%8,%9}, {%0,%1,%2,%3};\n"
        : "+f"(d[0]), "+f"(d[1]), "+f"(d[2]), "+f"(d[3])
        : "r"(a[0]), "r"(a[1]), "r"(a[2]), "r"(a[3]),
          "r"(b[0]), "r"(b[1]));
}

// ---------------- embedding ----------------
__global__ void embed_kernel(const float* __restrict__ in, const float* __restrict__ W,
                             const float* __restrict__ bias, const float* __restrict__ pe,
                             float* __restrict__ out)
{
    int idx = blockIdx.x * 256 + threadIdx.x;
    int d = idx & (Dn - 1);
    int t = idx >> 9;
    int s = t & (Sn - 1);
    float acc = bias[d] + pe[s * Dn + d];
#pragma unroll
    for (int i = 0; i < INn; i++)
        acc += in[t * INn + i] * W[i * Dn + d];
    out[idx] = acc;
}

// ---------------- TF32 GEMM with z-batching ----------------
// Tiles 128x64x16, 8 warps (4Mx2N), warp 32x32 = 2x4 m16n8k8.
// z-batch: zb=z/zdiv, zi=z%zdiv; A offset chosen from {aQ0,aKV0,aQ1,aKV1},
// B += zb*sBb + zi*sBi, bias += zb*sBiasB + zi*sBiasI, C += z*sC.
#define BM 128
#define BN 64
#define BK 16
#define APAD 20
#define BPAD 72

template <bool RELU>
__global__ __launch_bounds__(256)
void tgemm(const float* __restrict__ A, const float* __restrict__ Bm,
           const float* __restrict__ bias, float* __restrict__ C,
           int K, int lda, int ldb, int ldc, int zdiv,
           long long aQ0, long long aKV0, long long aQ1, long long aKV1,
           long long sBb, long long sBi, long long sBiasB, long long sBiasI,
           long long sC)
{
    __shared__ float As[2][BM][APAD];
    __shared__ float Bs[2][BK][BPAD];

    const int z = blockIdx.z;
    const int zb = z / zdiv, zi = z - zb * zdiv;
    A    += (zb == 0) ? (zi == 0 ? aQ0 : aKV0) : (zi == 0 ? aQ1 : aKV1);
    Bm   += zb * sBb + zi * sBi;
    bias += zb * sBiasB + zi * sBiasI;
    C    += (long long)z * sC;

    const int bm = blockIdx.y * BM;
    const int bn = blockIdx.x * BN;
    const int tid = threadIdx.x;
    const int lane = tid & 31;
    const int warp = tid >> 5;
    const int wm = (warp >> 1) * 32;
    const int wn = (warp & 1) * 32;
    const int gid = lane >> 2;
    const int ctid = lane & 3;

    const int a_kc4 = tid & 3;
    const int a_row0 = tid >> 2;
    const int b_nc4 = tid & 15;
    const int b_krow = tid >> 4;

    float acc[2][4][4];
#pragma unroll
    for (int i = 0; i < 2; i++)
#pragma unroll
        for (int j = 0; j < 4; j++)
#pragma unroll
            for (int q = 0; q < 4; q++) acc[i][j][q] = 0.f;

    const int NT = K / BK;
    float4 ra[2], rb;

#pragma unroll
    for (int v = 0; v < 2; v++)
        ra[v] = *(const float4*)&A[(long long)(bm + a_row0 + v * 64) * lda + a_kc4 * 4];
    rb = *(const float4*)&Bm[(long long)(b_krow) * ldb + bn + b_nc4 * 4];

#pragma unroll
    for (int v = 0; v < 2; v++) {
        float4 t = ra[v];
        t.x = to_tf32(t.x); t.y = to_tf32(t.y); t.z = to_tf32(t.z); t.w = to_tf32(t.w);
        *(float4*)&As[0][a_row0 + v * 64][a_kc4 * 4] = t;
    }
    {
        float4 t = rb;
        t.x = to_tf32(t.x); t.y = to_tf32(t.y); t.z = to_tf32(t.z); t.w = to_tf32(t.w);
        *(float4*)&Bs[0][b_krow][b_nc4 * 4] = t;
    }
    __syncthreads();

    for (int t = 0; t < NT; t++) {
        if (t + 1 < NT) {
            int k0 = (t + 1) * BK;
#pragma unroll
            for (int v = 0; v < 2; v++)
                ra[v] = *(const float4*)&A[(long long)(bm + a_row0 + v * 64) * lda + k0 + a_kc4 * 4];
            rb = *(const float4*)&Bm[(long long)(k0 + b_krow) * ldb + bn + b_nc4 * 4];
        }

        const int buf = t & 1;
#pragma unroll
        for (int kk = 0; kk < BK; kk += 8) {
            uint32_t afr[2][4];
#pragma unroll
            for (int i = 0; i < 2; i++) {
                int m = wm + i * 16;
                afr[i][0] = *(const uint32_t*)&As[buf][m + gid][kk + ctid];
                afr[i][1] = *(const uint32_t*)&As[buf][m + gid + 8][kk + ctid];
                afr[i][2] = *(const uint32_t*)&As[buf][m + gid][kk + ctid + 4];
                afr[i][3] = *(const uint32_t*)&As[buf][m + gid + 8][kk + ctid + 4];
            }
            uint32_t bfr[4][2];
#pragma unroll
            for (int j = 0; j < 4; j++) {
                int n = wn + j * 8 + gid;
                bfr[j][0] = *(const uint32_t*)&Bs[buf][kk + ctid][n];
                bfr[j][1] = *(const uint32_t*)&Bs[buf][kk + ctid + 4][n];
            }
#pragma unroll
            for (int i = 0; i < 2; i++)
#pragma unroll
                for (int j = 0; j < 4; j++)
                    mma_tf32(acc[i][j], afr[i], bfr[j]);
        }

        if (t + 1 < NT) {
            const int nbuf = (t + 1) & 1;
#pragma unroll
            for (int v = 0; v < 2; v++) {
                float4 tt = ra[v];
                tt.x = to_tf32(tt.x); tt.y = to_tf32(tt.y); tt.z = to_tf32(tt.z); tt.w = to_tf32(tt.w);
                *(float4*)&As[nbuf][a_row0 + v * 64][a_kc4 * 4] = tt;
            }
            float4 tt = rb;
            tt.x = to_tf32(tt.x); tt.y = to_tf32(tt.y); tt.z = to_tf32(tt.z); tt.w = to_tf32(tt.w);
            *(float4*)&Bs[nbuf][b_krow][b_nc4 * 4] = tt;
        }
        __syncthreads();
    }

#pragma unroll
    for (int i = 0; i < 2; i++) {
        int row0 = bm + wm + i * 16 + gid;
        int row1 = row0 + 8;
#pragma unroll
        for (int j = 0; j < 4; j++) {
            int col = bn + wn + j * 8 + 2 * ctid;
            float bv0 = bias[col];
            float bv1 = bias[col + 1];
            float2 o0, o1;
            o0.x = acc[i][j][0] + bv0;
            o0.y = acc[i][j][1] + bv1;
            o1.x = acc[i][j][2] + bv0;
            o1.y = acc[i][j][3] + bv1;
            if (RELU) {
                o0.x = fmaxf(o0.x, 0.f); o0.y = fmaxf(o0.y, 0.f);
                o1.x = fmaxf(o1.x, 0.f); o1.y = fmaxf(o1.y, 0.f);
            }
            *(float2*)&C[(long long)row0 * ldc + col] = o0;
            *(float2*)&C[(long long)row1 * ldc + col] = o1;
        }
    }
}

// ---------------- flash attention ----------------
// grid (S/128, B*H, 2blk); 256 threads = 8 warps, warp strip = 16 q-rows.
// Q tile 128x64 staged (tf32), KV tiles 64x64, online softmax, ctx in token layout.
// Smem strides: 68 for row-major frag reads (4g+c banks), 72 for V col reads (8c+g banks).
#define FA_SMEM_BYTES ((128*68 + 128*68 + 64*68 + 64*72) * 4)

__global__ __launch_bounds__(256, 2)
void flash_kernel(const float* __restrict__ qkv, float* __restrict__ ctx)
{
    extern __shared__ float sm[];
    float* Qs = sm;                 // [128][68]
    float* Ps = sm + 128 * 68;      // [128][68]
    float* Ks = Ps + 128 * 68;      // [64][68]
    float* Vs = Ks + 64 * 68;       // [64][72]

    const int qt = blockIdx.x, bh = blockIdx.y, zb = blockIdx.z;
    const int b = bh >> 3, h = bh & 7;
    const float* Qg = qkv + (long long)zb * 3 * RR;
    const float* Kg = Qg + RR;
    const float* Vg = Qg + 2 * RR;
    const long long tq  = (long long)b * Sn + qt * 128;
    const long long tk0 = (long long)b * Sn;
    const int hc = h * DKn;

    const int tid = threadIdx.x, lane = tid & 31, warp = tid >> 5;
    const int g = lane >> 2, c = lane & 3;
    const int wrow = warp * 16;

    // stage Q (tf32)
#pragma unroll
    for (int i = 0; i < 8; i++) {
        int f = tid + i * 256, row = f >> 4, c4 = f & 15;
        float4 t = *(const float4*)&Qg[(tq + row) * Dn + hc + c4 * 4];
        t.x = to_tf32(t.x); t.y = to_tf32(t.y); t.z = to_tf32(t.z); t.w = to_tf32(t.w);
        *(float4*)&Qs[row * 68 + c4 * 4] = t;
    }

    float m0 = -1e30f, m1 = -1e30f, l0 = 0.f, l1 = 0.f;
    float oacc[8][4];
#pragma unroll
    for (int j = 0; j < 8; j++)
#pragma unroll
        for (int q = 0; q < 4; q++) oacc[j][q] = 0.f;

    for (int t = 0; t < Sn / 64; t++) {
        __syncthreads();
#pragma unroll
        for (int i = 0; i < 4; i++) {
            int f = tid + i * 256, row = f >> 4, c4 = f & 15;
            long long ga = (tk0 + t * 64 + row) * Dn + hc + c4 * 4;
            float4 kv = *(const float4*)&Kg[ga];
            kv.x = to_tf32(kv.x); kv.y = to_tf32(kv.y); kv.z = to_tf32(kv.z); kv.w = to_tf32(kv.w);
            *(float4*)&Ks[row * 68 + c4 * 4] = kv;
            float4 vv = *(const float4*)&Vg[ga];
            vv.x = to_tf32(vv.x); vv.y = to_tf32(vv.y); vv.z = to_tf32(vv.z); vv.w = to_tf32(vv.w);
            *(float4*)&Vs[row * 72 + c4 * 4] = vv;
        }
        __syncthreads();

        // S = Q K^T (scaled)
        float sacc[8][4];
#pragma unroll
        for (int j = 0; j < 8; j++)
#pragma unroll
            for (int q = 0; q < 4; q++) sacc[j][q] = 0.f;
#pragma unroll
        for (int s = 0; s < 8; s++) {
            uint32_t af[4];
            af[0] = *(const uint32_t*)&Qs[(wrow + g) * 68 + s * 8 + c];
            af[1] = *(const uint32_t*)&Qs[(wrow + g + 8) * 68 + s * 8 + c];
            af[2] = *(const uint32_t*)&Qs[(wrow + g) * 68 + s * 8 + c + 4];
            af[3] = *(const uint32_t*)&Qs[(wrow + g + 8) * 68 + s * 8 + c + 4];
#pragma unroll
            for (int j = 0; j < 8; j++) {
                uint32_t bf[2];
                bf[0] = *(const uint32_t*)&Ks[(j * 8 + g) * 68 + s * 8 + c];
                bf[1] = *(const uint32_t*)&Ks[(j * 8 + g) * 68 + s * 8 + c + 4];
                mma_tf32(sacc[j], af, bf);
            }
        }

        // online softmax (rows g and g+8 of warp strip)
        float rm0 = -1e30f, rm1 = -1e30f;
#pragma unroll
        for (int j = 0; j < 8; j++) {
            sacc[j][0] *= 0.125f; sacc[j][1] *= 0.125f;
            sacc[j][2] *= 0.125f; sacc[j][3] *= 0.125f;
            rm0 = fmaxf(rm0, fmaxf(sacc[j][0], sacc[j][1]));
            rm1 = fmaxf(rm1, fmaxf(sacc[j][2], sacc[j][3]));
        }
        rm0 = fmaxf(rm0, __shfl_xor_sync(0xffffffffu, rm0, 1));
        rm0 = fmaxf(rm0, __shfl_xor_sync(0xffffffffu, rm0, 2));
        rm1 = fmaxf(rm1, __shfl_xor_sync(0xffffffffu, rm1, 1));
        rm1 = fmaxf(rm1, __shfl_xor_sync(0xffffffffu, rm1, 2));
        float mn0 = fmaxf(m0, rm0), mn1 = fmaxf(m1, rm1);
        float sc0 = __expf(m0 - mn0), sc1 = __expf(m1 - mn1);
        m0 = mn0; m1 = mn1;
        float ps0 = 0.f, ps1 = 0.f;
#pragma unroll
        for (int j = 0; j < 8; j++) {
            sacc[j][0] = __expf(sacc[j][0] - m0);
            sacc[j][1] = __expf(sacc[j][1] - m0);
            sacc[j][2] = __expf(sacc[j][2] - m1);
            sacc[j][3] = __expf(sacc[j][3] - m1);
            ps0 += sacc[j][0] + sacc[j][1];
            ps1 += sacc[j][2] + sacc[j][3];
            oacc[j][0] *= sc0; oacc[j][1] *= sc0;
            oacc[j][2] *= sc1; oacc[j][3] *= sc1;
        }
        ps0 += __shfl_xor_sync(0xffffffffu, ps0, 1);
        ps0 += __shfl_xor_sync(0xffffffffu, ps0, 2);
        ps1 += __shfl_xor_sync(0xffffffffu, ps1, 1);
        ps1 += __shfl_xor_sync(0xffffffffu, ps1, 2);
        l0 = l0 * sc0 + ps0;
        l1 = l1 * sc1 + ps1;

        // P -> smem (warp-private strip), tf32
#pragma unroll
        for (int j = 0; j < 8; j++) {
            float2 p01, p23;
            p01.x = to_tf32(sacc[j][0]); p01.y = to_tf32(sacc[j][1]);
            p23.x = to_tf32(sacc[j][2]); p23.y = to_tf32(sacc[j][3]);
            *(float2*)&Ps[(wrow + g) * 68 + j * 8 + 2 * c] = p01;
            *(float2*)&Ps[(wrow + g + 8) * 68 + j * 8 + 2 * c] = p23;
        }
        __syncwarp();

        // O += P V
#pragma unroll
        for (int s = 0; s < 8; s++) {
            uint32_t af[4];
            af[0] = *(const uint32_t*)&Ps[(wrow + g) * 68 + s * 8 + c];
            af[1] = *(const uint32_t*)&Ps[(wrow + g + 8) * 68 + s * 8 + c];
            af[2] = *(const uint32_t*)&Ps[(wrow + g) * 68 + s * 8 + c + 4];
            af[3] = *(const uint32_t*)&Ps[(wrow + g + 8) * 68 + s * 8 + c + 4];
#pragma unroll
            for (int j = 0; j < 8; j++) {
                uint32_t bf[2];
                bf[0] = *(const uint32_t*)&Vs[(s * 8 + c) * 72 + j * 8 + g];
                bf[1] = *(const uint32_t*)&Vs[(s * 8 + c + 4) * 72 + j * 8 + g];
                mma_tf32(oacc[j], af, bf);
            }
        }
    }

    float inv0 = 1.f / l0, inv1 = 1.f / l1;
    float* Co = ctx + (long long)zb * RR;
#pragma unroll
    for (int j = 0; j < 8; j++) {
        float2 o01, o23;
        o01.x = oacc[j][0] * inv0; o01.y = oacc[j][1] * inv0;
        o23.x = oacc[j][2] * inv1; o23.y = oacc[j][3] * inv1;
        *(float2*)&Co[(tq + wrow + g) * Dn + hc + j * 8 + 2 * c] = o01;
        *(float2*)&Co[(tq + wrow + g + 8) * Dn + hc + j * 8 + 2 * c] = o23;
    }
}

// ---------------- add residual + layernorm, batched over 2 channels ----------------
__global__ void add_ln_kernel(const float* __restrict__ x, const float* __restrict__ r,
                              const float* __restrict__ g, const float* __restrict__ be,
                              float* __restrict__ out)
{
    long long row = blockIdx.x;                 // 0 .. 2*BSn-1
    const int chan = (row >= BSn) ? 1 : 0;
    const float* gp = g + chan * Dn;
    const float* bp = be + chan * Dn;
    const float* xp = x + row * Dn;
    const float* rp = r + row * Dn;
    int t = threadIdx.x;
    float v[4]; float s = 0.f, s2 = 0.f;
#pragma unroll
    for (int i = 0; i < 4; i++) {
        int cc = t + i * 128;
        v[i] = xp[cc] + rp[cc];
        s += v[i]; s2 += v[i] * v[i];
    }
    __shared__ float rs[128], rs2[128];
    rs[t] = s; rs2[t] = s2; __syncthreads();
#pragma unroll
    for (int o = 64; o > 0; o >>= 1) {
        if (t < o) { rs[t] += rs[t + o]; rs2[t] += rs2[t + o]; }
        __syncthreads();
    }
    float mean = rs[0] * (1.f / Dn);
    float var  = rs2[0] * (1.f / Dn) - mean * mean;
    float rstd = rsqrtf(var + 1e-5f);
    float* op = out + row * Dn;
#pragma unroll
    for (int i = 0; i < 4; i++) {
        int cc = t + i * 128;
        op[cc] = (v[i] - mean) * rstd * gp[cc] + bp[cc];
    }
}

// ---------------- pool + heads ----------------
__global__ void pool_kernel(const float* __restrict__ x, float* __restrict__ fused)
{
    int idx = blockIdx.x * 256 + threadIdx.x;
    int b = idx >> 10;
    int c = idx & 1023;
    const float* src = (c < Dn) ? (x + (long long)b * Sn * Dn + c)
                                : (x + RR + (long long)b * Sn * Dn + (c - Dn));
    float s = 0.f;
    for (int t = 0; t < Sn; t++) s += src[(long long)t * Dn];
    fused[idx] = s * (1.f / Sn);
}

__global__ void head_kernel(const float* __restrict__ fused,
                            const float* __restrict__ w1, const float* __restrict__ b1,
                            const float* __restrict__ w2, const float* __restrict__ b2,
                            float* __restrict__ out)
{
    __shared__ float sf[2 * Dn];
    int b = blockIdx.x, t = threadIdx.x;
    sf[t]      = fused[b * 2 * Dn + t];
    sf[t + Dn] = fused[b * 2 * Dn + t + Dn];
    __syncthreads();
    float h = b1[t];
    for (int k = 0; k < 2 * Dn; k++)
        h += sf[k] * w1[k * Dn + t];
    h = fmaxf(h, 0.f);
    __shared__ float r0[512], r1[512];
    r0[t] = h * w2[t * 2 + 0];
    r1[t] = h * w2[t * 2 + 1];
    __syncthreads();
#pragma unroll
    for (int o = 256; o > 0; o >>= 1) {
        if (t < o) { r0[t] += r0[t + o]; r1[t] += r1[t + o]; }
        __syncthreads();
    }
    if (t == 0) {
        out[b * 2 + 0] = r0[0] + b2[0];
        out[b * 2 + 1] = r1[0] + b2[1];
    }
}

extern "C" void kernel_launch(void* const* d_in, const int* in_sizes, int n_in,
                              void* d_out, int out_size)
{
    const float* left_wrist  = (const float*)d_in[0];
    const float* right_wrist = (const float*)d_in[1];
    const float* Wl = (const float*)d_in[2];
    const float* bl = (const float*)d_in[3];
    const float* Wr = (const float*)d_in[4];
    const float* br = (const float*)d_in[5];
    const float* pe = (const float*)d_in[6];
    const float* mha_w    = (const float*)d_in[7];
    const float* mha_b    = (const float*)d_in[8];
    const float* mha_ln_g = (const float*)d_in[9];
    const float* mha_ln_b = (const float*)d_in[10];
    const float* ff_w1    = (const float*)d_in[11];
    const float* ff_b1    = (const float*)d_in[12];
    const float* ff_w2    = (const float*)d_in[13];
    const float* ff_b2    = (const float*)d_in[14];
    const float* ff_ln_g  = (const float*)d_in[15];
    const float* ff_ln_b  = (const float*)d_in[16];
    const float* h1_w1 = (const float*)d_in[17];
    const float* h1_b1 = (const float*)d_in[18];
    const float* h1_w2 = (const float*)d_in[19];
    const float* h1_b2 = (const float*)d_in[20];
    const float* h2_w1 = (const float*)d_in[21];
    const float* h2_b1 = (const float*)d_in[22];
    const float* h2_w2 = (const float*)d_in[23];
    const float* h2_b2 = (const float*)d_in[24];
    float* out = (float*)d_out;

    float *pX, *pC, *pQKV, *pCtx, *pO, *pFfh, *pFused;
    cudaGetSymbolAddress((void**)&pX,    gbuf_x);
    cudaGetSymbolAddress((void**)&pC,    gbuf_c);
    cudaGetSymbolAddress((void**)&pQKV,  gbuf_qkv);
    cudaGetSymbolAddress((void**)&pCtx,  gbuf_ctx);
    cudaGetSymbolAddress((void**)&pO,    gbuf_o);
    cudaGetSymbolAddress((void**)&pFfh,  gbuf_ffh);
    cudaGetSymbolAddress((void**)&pFused, gbuf_fused);

    cudaFuncSetAttribute(flash_kernel, cudaFuncAttributeMaxDynamicSharedMemorySize, FA_SMEM_BYTES);

    embed_kernel<<<(BSn * Dn) / 256, 256>>>(left_wrist,  Wl, bl, pe, pX);
    embed_kernel<<<(BSn * Dn) / 256, 256>>>(right_wrist, Wr, br, pe, pX + RR);

    const dim3 gProj(Dn / BN, BSn / BM, 2);      // 8 x 32 x 2
    const dim3 gQKV(Dn / BN, BSn / BM, 6);       // 8 x 32 x 6
    const dim3 gFlash(Sn / 128, Bn * Hn, 2);     // 8 x 32 x 2
    const dim3 gFf1(Fn / BN, BSn / BM, 2);       // 32 x 32 x 2

    for (int l = 0; l < Ln; l++) {
        const float* w_base  = mha_w    + (long long)l * 4 * 4 * Dn * Dn;
        const float* b_base  = mha_b    + (long long)l * 4 * 4 * Dn;
        const float* lg_base = mha_ln_g + (long long)l * 4 * Dn;
        const float* lb_base = mha_ln_b + (long long)l * 4 * Dn;

        // ---- cross attention (blocks 0,1) ----
        tgemm<false><<<gQKV, 256>>>(pX, w_base, b_base, pQKV,
            Dn, Dn, Dn, Dn, 3,
            0, RR, RR, 0,
            4LL * Dn * Dn, (long long)Dn * Dn, 4LL * Dn, (long long)Dn, RR);
        flash_kernel<<<gFlash, 256, FA_SMEM_BYTES>>>(pQKV, pCtx);
        tgemm<false><<<gProj, 256>>>(pCtx, w_base + 3LL * Dn * Dn, b_base + 3LL * Dn, pO,
            Dn, Dn, Dn, Dn, 1,
            0, 0, RR, 0,
            4LL * Dn * Dn, 0, 4LL * Dn, 0, RR);
        add_ln_kernel<<<2 * BSn, 128>>>(pO, pX, lg_base, lb_base, pC);

        // ---- self attention (blocks 2,3) ----
        tgemm<false><<<gQKV, 256>>>(pC, w_base + 2LL * 4 * Dn * Dn, b_base + 2LL * 4 * Dn, pQKV,
            Dn, Dn, Dn, Dn, 3,
            0, 0, RR, RR,
            4LL * Dn * Dn, (long long)Dn * Dn, 4LL * Dn, (long long)Dn, RR);
        flash_kernel<<<gFlash, 256, FA_SMEM_BYTES>>>(pQKV, pCtx);
        tgemm<false><<<gProj, 256>>>(pCtx, w_base + (2LL * 4 + 3) * Dn * Dn, b_base + (2LL * 4 + 3) * Dn, pO,
            Dn, Dn, Dn, Dn, 1,
            0, 0, RR, 0,
            4LL * Dn * Dn, 0, 4LL * Dn, 0, RR);
        add_ln_kernel<<<2 * BSn, 128>>>(pO, pC, lg_base + 2 * Dn, lb_base + 2 * Dn, pX);

        // ---- FFNs ----
        tgemm<true><<<gFf1, 256>>>(pX, ff_w1 + (long long)l * 2 * Dn * Fn, ff_b1 + (long long)l * 2 * Fn, pFfh,
            Dn, Dn, Fn, Fn, 1,
            0, 0, RR, 0,
            (long long)Dn * Fn, 0, (long long)Fn, 0, (long long)BSn * Fn);
        tgemm<false><<<gProj, 256>>>(pFfh, ff_w2 + (long long)l * 2 * Fn * Dn, ff_b2 + (long long)l * 2 * Dn, pO,
            Fn, Fn, Dn, Dn, 1,
            0, 0, (long long)BSn * Fn, 0,
            (long long)Fn * Dn, 0, (long long)Dn, 0, RR);
        add_ln_kernel<<<2 * BSn, 128>>>(pO, pX, ff_ln_g + (long long)l * 2 * Dn, ff_ln_b + (long long)l * 2 * Dn, pX);
    }

    pool_kernel<<<(Bn * 2 * Dn) / 256, 256>>>(pX, pFused);
    head_kernel<<<Bn, 512>>>(pFused, h1_w1, h1_b1, h1_w2, h1_b2, out);
    head_kernel<<<Bn, 512>>>(pFused, h2_w1, h2_b1, h2_w2, h2_b2, out + Bn * 2);
}

// round 4
// speedup vs baseline: 5.4294x; 1.2727x over previous
#include <cuda_runtime.h>
#include <cstdint>

// Problem constants
#define Bn   4
#define Sn   1024
#define INn  6
#define Dn   512
#define Hn   8
#define Ln   4
#define Fn   2048
#define DKn  64
#define BSn  (Bn * Sn)   // 4096 tokens
#define RR   ((long long)BSn * Dn)

// ---------------- scratch ----------------
__device__ float gbuf_x  [2 * BSn * Dn];   // left | right
__device__ float gbuf_c  [2 * BSn * Dn];   // lc | rc
__device__ float gbuf_qkv[6 * BSn * Dn];   // [blk][q/k/v][token][D]
__device__ float gbuf_ctx[2 * BSn * Dn];
__device__ float gbuf_o  [2 * BSn * Dn];
__device__ float gbuf_ffh[2 * BSn * Fn];
__device__ float gbuf_fused[Bn * 2 * Dn];

__device__ __forceinline__ float to_tf32(float x) {
    float r;
    asm("cvt.rna.tf32.f32 %0, %1;" : "=f"(r) : "f"(x));
    return r;
}

__device__ __forceinline__ void mma_tf32(float* d, const uint32_t* a, const uint32_t* b) {
    asm volatile(
        "mma.sync.aligned.m16n8k8.row.col.f32.tf32.tf32.f32 "
        "{%0,%1,%2,%3}, {%4,%5,%6,%7}, {%8,%9}, {%0,%1,%2,%3};\n"
        : "+f"(d[0]), "+f"(d[1]), "+f"(d[2]), "+f"(d[3])
        : "r"(a[0]), "r"(a[1]), "r"(a[2]), "r"(a[3]),
          "r"(b[0]), "r"(b[1]));
}

#define CP_ASYNC16(dst, src) \
    asm volatile("cp.async.cg.shared.global [%0], [%1], 16;" :: "r"(dst), "l"(src))
#define CP_COMMIT() asm volatile("cp.async.commit_group;")

// ---------------- embedding ----------------
__global__ void embed_kernel(const float* __restrict__ in, const float* __restrict__ W,
                             const float* __restrict__ bias, const float* __restrict__ pe,
                             float* __restrict__ out)
{
    int idx = blockIdx.x * 256 + threadIdx.x;
    int d = idx & (Dn - 1);
    int t = idx >> 9;
    int s = t & (Sn - 1);
    float acc = bias[d] + pe[s * Dn + d];
#pragma unroll
    for (int i = 0; i < INn; i++)
        acc += in[t * INn + i] * W[i * Dn + d];
    out[idx] = acc;
}

// ---------------- TF32 GEMM, 128x128x16 tiles ----------------
// 8 warps (2M x 4N), warp tile 64x32 = 4x4 m16n8k8 atoms.
#define BM 128
#define BN 128
#define BK 16
#define APAD 20
#define BPAD 136

template <bool RELU>
__global__ __launch_bounds__(256, 2)
void tgemm(const float* __restrict__ A, const float* __restrict__ Bm,
           const float* __restrict__ bias, float* __restrict__ C,
           int K, int lda, int ldb, int ldc, int zdiv,
           long long aQ0, long long aKV0, long long aQ1, long long aKV1,
           long long sBb, long long sBi, long long sBiasB, long long sBiasI,
           long long sC)
{
    __shared__ float As[2][BM][APAD];
    __shared__ float Bs[2][BK][BPAD];

    const int z = blockIdx.z;
    const int zb = z / zdiv, zi = z - zb * zdiv;
    A    += (zb == 0) ? (zi == 0 ? aQ0 : aKV0) : (zi == 0 ? aQ1 : aKV1);
    Bm   += zb * sBb + zi * sBi;
    bias += zb * sBiasB + zi * sBiasI;
    C    += (long long)z * sC;

    const int bm = blockIdx.y * BM;
    const int bn = blockIdx.x * BN;
    const int tid = threadIdx.x;
    const int lane = tid & 31;
    const int warp = tid >> 5;
    const int wm = (warp >> 2) * 64;
    const int wn = (warp & 3) * 32;
    const int g = lane >> 2;
    const int c = lane & 3;

    const int a_kc4 = tid & 3;
    const int a_row0 = tid >> 2;      // 0..63, +64
    const int b_nc4 = tid & 31;       // 0..31 float4 along N
    const int b_krow = tid >> 5;      // 0..7, +8

    float acc[4][4][4];
#pragma unroll
    for (int i = 0; i < 4; i++)
#pragma unroll
        for (int j = 0; j < 4; j++)
#pragma unroll
            for (int q = 0; q < 4; q++) acc[i][j][q] = 0.f;

    const int NT = K / BK;
    float4 ra[2], rb[2];

#pragma unroll
    for (int v = 0; v < 2; v++)
        ra[v] = *(const float4*)&A[(long long)(bm + a_row0 + v * 64) * lda + a_kc4 * 4];
#pragma unroll
    for (int v = 0; v < 2; v++)
        rb[v] = *(const float4*)&Bm[(long long)(b_krow + v * 8) * ldb + bn + b_nc4 * 4];

#pragma unroll
    for (int v = 0; v < 2; v++) {
        float4 t = ra[v];
        t.x = to_tf32(t.x); t.y = to_tf32(t.y); t.z = to_tf32(t.z); t.w = to_tf32(t.w);
        *(float4*)&As[0][a_row0 + v * 64][a_kc4 * 4] = t;
    }
#pragma unroll
    for (int v = 0; v < 2; v++) {
        float4 t = rb[v];
        t.x = to_tf32(t.x); t.y = to_tf32(t.y); t.z = to_tf32(t.z); t.w = to_tf32(t.w);
        *(float4*)&Bs[0][b_krow + v * 8][b_nc4 * 4] = t;
    }
    __syncthreads();

    for (int t = 0; t < NT; t++) {
        if (t + 1 < NT) {
            int k0 = (t + 1) * BK;
#pragma unroll
            for (int v = 0; v < 2; v++)
                ra[v] = *(const float4*)&A[(long long)(bm + a_row0 + v * 64) * lda + k0 + a_kc4 * 4];
#pragma unroll
            for (int v = 0; v < 2; v++)
                rb[v] = *(const float4*)&Bm[(long long)(k0 + b_krow + v * 8) * ldb + bn + b_nc4 * 4];
        }

        const int buf = t & 1;
#pragma unroll
        for (int kk = 0; kk < BK; kk += 8) {
            uint32_t afr[4][4];
#pragma unroll
            for (int i = 0; i < 4; i++) {
                int m = wm + i * 16;
                afr[i][0] = *(const uint32_t*)&As[buf][m + g][kk + c];
                afr[i][1] = *(const uint32_t*)&As[buf][m + g + 8][kk + c];
                afr[i][2] = *(const uint32_t*)&As[buf][m + g][kk + c + 4];
                afr[i][3] = *(const uint32_t*)&As[buf][m + g + 8][kk + c + 4];
            }
            uint32_t bfr[4][2];
#pragma unroll
            for (int j = 0; j < 4; j++) {
                int n = wn + j * 8 + g;
                bfr[j][0] = *(const uint32_t*)&Bs[buf][kk + c][n];
                bfr[j][1] = *(const uint32_t*)&Bs[buf][kk + c + 4][n];
            }
#pragma unroll
            for (int i = 0; i < 4; i++)
#pragma unroll
                for (int j = 0; j < 4; j++)
                    mma_tf32(acc[i][j], afr[i], bfr[j]);
        }

        if (t + 1 < NT) {
            const int nbuf = (t + 1) & 1;
#pragma unroll
            for (int v = 0; v < 2; v++) {
                float4 tt = ra[v];
                tt.x = to_tf32(tt.x); tt.y = to_tf32(tt.y); tt.z = to_tf32(tt.z); tt.w = to_tf32(tt.w);
                *(float4*)&As[nbuf][a_row0 + v * 64][a_kc4 * 4] = tt;
            }
#pragma unroll
            for (int v = 0; v < 2; v++) {
                float4 tt = rb[v];
                tt.x = to_tf32(tt.x); tt.y = to_tf32(tt.y); tt.z = to_tf32(tt.z); tt.w = to_tf32(tt.w);
                *(float4*)&Bs[nbuf][b_krow + v * 8][b_nc4 * 4] = tt;
            }
        }
        __syncthreads();
    }

#pragma unroll
    for (int i = 0; i < 4; i++) {
        int row0 = bm + wm + i * 16 + g;
        int row1 = row0 + 8;
#pragma unroll
        for (int j = 0; j < 4; j++) {
            int col = bn + wn + j * 8 + 2 * c;
            float bv0 = bias[col];
            float bv1 = bias[col + 1];
            float2 o0, o1;
            o0.x = acc[i][j][0] + bv0;
            o0.y = acc[i][j][1] + bv1;
            o1.x = acc[i][j][2] + bv0;
            o1.y = acc[i][j][3] + bv1;
            if (RELU) {
                o0.x = fmaxf(o0.x, 0.f); o0.y = fmaxf(o0.y, 0.f);
                o1.x = fmaxf(o1.x, 0.f); o1.y = fmaxf(o1.y, 0.f);
            }
            *(float2*)&C[(long long)row0 * ldc + col] = o0;
            *(float2*)&C[(long long)row1 * ldc + col] = o1;
        }
    }
}

// ---------------- flash attention (cp.async double-buffered KV, shfl P) ----------------
// grid (S/128, B*H, 2); 256 threads = 8 warps, warp strip = 16 q-rows.
// Smem: Qs[128][68] (tf32), Ks[2][64][68], Vs[2][64][72] (raw fp32 -> truncated tf32 in mma).
#define FA_SMEM_BYTES ((128*68 + 2*64*68 + 2*64*72) * 4)

__global__ __launch_bounds__(256, 2)
void flash_kernel(const float* __restrict__ qkv, float* __restrict__ ctx)
{
    extern __shared__ float sm[];
    float* Qs = sm;                      // [128][68]
    float* Ks = sm + 128 * 68;           // [2][64][68]
    float* Vs = Ks + 2 * 64 * 68;        // [2][64][72]

    const int qt = blockIdx.x, bh = blockIdx.y, zb = blockIdx.z;
    const int b = bh >> 3, h = bh & 7;
    const float* Qg = qkv + (long long)zb * 3 * RR;
    const float* Kg = Qg + RR;
    const float* Vg = Qg + 2 * RR;
    const long long tq  = (long long)b * Sn + qt * 128;
    const long long tk0 = (long long)b * Sn;
    const int hc = h * DKn;

    const int tid = threadIdx.x, lane = tid & 31, warp = tid >> 5;
    const int g = lane >> 2, c = lane & 3;
    const int wrow = warp * 16;
    const int src0 = (lane & 28) | (c >> 1);
    const int src2 = src0 + 2;
    const bool codd = (c & 1) != 0;

    // stage Q (tf32, RNA)
#pragma unroll
    for (int i = 0; i < 8; i++) {
        int f = tid + i * 256, row = f >> 4, c4 = f & 15;
        float4 t = *(const float4*)&Qg[(tq + row) * Dn + hc + c4 * 4];
        t.x = to_tf32(t.x); t.y = to_tf32(t.y); t.z = to_tf32(t.z); t.w = to_tf32(t.w);
        *(float4*)&Qs[row * 68 + c4 * 4] = t;
    }

    // cp.async prefetch of K/V tile t into buffer buf
    auto prefetch = [&](int t, int buf) {
        const long long rbase = tk0 + t * 64;
#pragma unroll
        for (int i = 0; i < 4; i++) {
            int f = tid + i * 256, r = f >> 4, c4 = f & 15;
            const float* gk = &Kg[(rbase + r) * Dn + hc + c4 * 4];
            const float* gv = &Vg[(rbase + r) * Dn + hc + c4 * 4];
            uint32_t sk = (uint32_t)__cvta_generic_to_shared(&Ks[(buf * 64 + r) * 68 + c4 * 4]);
            uint32_t sv = (uint32_t)__cvta_generic_to_shared(&Vs[(buf * 64 + r) * 72 + c4 * 4]);
            CP_ASYNC16(sk, gk);
            CP_ASYNC16(sv, gv);
        }
        CP_COMMIT();
    };

    prefetch(0, 0);
    prefetch(1, 1);

    float m0 = -1e30f, m1 = -1e30f, l0 = 0.f, l1 = 0.f;
    float oacc[8][4];
#pragma unroll
    for (int j = 0; j < 8; j++)
#pragma unroll
        for (int q = 0; q < 4; q++) oacc[j][q] = 0.f;

    for (int t = 0; t < Sn / 64; t++) {
        if (t < Sn / 64 - 1) asm volatile("cp.async.wait_group 1;");
        else                 asm volatile("cp.async.wait_group 0;");
        __syncthreads();

        const float* Kb = &Ks[(t & 1) * 64 * 68];
        const float* Vb = &Vs[(t & 1) * 64 * 72];

        // S = Q K^T
        float sacc[8][4];
#pragma unroll
        for (int j = 0; j < 8; j++)
#pragma unroll
            for (int q = 0; q < 4; q++) sacc[j][q] = 0.f;
#pragma unroll
        for (int s = 0; s < 8; s++) {
            uint32_t af[4];
            af[0] = *(const uint32_t*)&Qs[(wrow + g) * 68 + s * 8 + c];
            af[1] = *(const uint32_t*)&Qs[(wrow + g + 8) * 68 + s * 8 + c];
            af[2] = *(const uint32_t*)&Qs[(wrow + g) * 68 + s * 8 + c + 4];
            af[3] = *(const uint32_t*)&Qs[(wrow + g + 8) * 68 + s * 8 + c + 4];
#pragma unroll
            for (int j = 0; j < 8; j++) {
                uint32_t bf[2];
                bf[0] = *(const uint32_t*)&Kb[(j * 8 + g) * 68 + s * 8 + c];
                bf[1] = *(const uint32_t*)&Kb[(j * 8 + g) * 68 + s * 8 + c + 4];
                mma_tf32(sacc[j], af, bf);
            }
        }

        // online softmax (rows g and g+8)
        float rm0 = -1e30f, rm1 = -1e30f;
#pragma unroll
        for (int j = 0; j < 8; j++) {
            sacc[j][0] *= 0.125f; sacc[j][1] *= 0.125f;
            sacc[j][2] *= 0.125f; sacc[j][3] *= 0.125f;
            rm0 = fmaxf(rm0, fmaxf(sacc[j][0], sacc[j][1]));
            rm1 = fmaxf(rm1, fmaxf(sacc[j][2], sacc[j][3]));
        }
        rm0 = fmaxf(rm0, __shfl_xor_sync(0xffffffffu, rm0, 1));
        rm0 = fmaxf(rm0, __shfl_xor_sync(0xffffffffu, rm0, 2));
        rm1 = fmaxf(rm1, __shfl_xor_sync(0xffffffffu, rm1, 1));
        rm1 = fmaxf(rm1, __shfl_xor_sync(0xffffffffu, rm1, 2));
        float mn0 = fmaxf(m0, rm0), mn1 = fmaxf(m1, rm1);
        float sc0 = __expf(m0 - mn0), sc1 = __expf(m1 - mn1);
        m0 = mn0; m1 = mn1;
        float ps0 = 0.f, ps1 = 0.f;
#pragma unroll
        for (int j = 0; j < 8; j++) {
            sacc[j][0] = __expf(sacc[j][0] - m0);
            sacc[j][1] = __expf(sacc[j][1] - m0);
            sacc[j][2] = __expf(sacc[j][2] - m1);
            sacc[j][3] = __expf(sacc[j][3] - m1);
            ps0 += sacc[j][0] + sacc[j][1];
            ps1 += sacc[j][2] + sacc[j][3];
            oacc[j][0] *= sc0; oacc[j][1] *= sc0;
            oacc[j][2] *= sc1; oacc[j][3] *= sc1;
        }
        ps0 += __shfl_xor_sync(0xffffffffu, ps0, 1);
        ps0 += __shfl_xor_sync(0xffffffffu, ps0, 2);
        ps1 += __shfl_xor_sync(0xffffffffu, ps1, 1);
        ps1 += __shfl_xor_sync(0xffffffffu, ps1, 2);
        l0 = l0 * sc0 + ps0;
        l1 = l1 * sc1 + ps1;

        // O += P V : A-fragment of P built by warp shuffles from S-fragment
#pragma unroll
        for (int s = 0; s < 8; s++) {
            float v0 = __shfl_sync(0xffffffffu, sacc[s][0], src0);
            float v1 = __shfl_sync(0xffffffffu, sacc[s][1], src0);
            float v2 = __shfl_sync(0xffffffffu, sacc[s][2], src0);
            float v3 = __shfl_sync(0xffffffffu, sacc[s][3], src0);
            float w0 = __shfl_sync(0xffffffffu, sacc[s][0], src2);
            float w1 = __shfl_sync(0xffffffffu, sacc[s][1], src2);
            float w2 = __shfl_sync(0xffffffffu, sacc[s][2], src2);
            float w3 = __shfl_sync(0xffffffffu, sacc[s][3], src2);
            uint32_t af[4];
            af[0] = __float_as_uint(to_tf32(codd ? v1 : v0));
            af[1] = __float_as_uint(to_tf32(codd ? v3 : v2));
            af[2] = __float_as_uint(to_tf32(codd ? w1 : w0));
            af[3] = __float_as_uint(to_tf32(codd ? w3 : w2));
#pragma unroll
            for (int j = 0; j < 8; j++) {
                uint32_t bf[2];
                bf[0] = *(const uint32_t*)&Vb[(s * 8 + c) * 72 + j * 8 + g];
                bf[1] = *(const uint32_t*)&Vb[(s * 8 + c + 4) * 72 + j * 8 + g];
                mma_tf32(oacc[j], af, bf);
            }
        }

        __syncthreads();
        if (t + 2 < Sn / 64) prefetch(t + 2, t & 1);
    }

    float inv0 = 1.f / l0, inv1 = 1.f / l1;
    float* Co = ctx + (long long)zb * RR;
#pragma unroll
    for (int j = 0; j < 8; j++) {
        float2 o01, o23;
        o01.x = oacc[j][0] * inv0; o01.y = oacc[j][1] * inv0;
        o23.x = oacc[j][2] * inv1; o23.y = oacc[j][3] * inv1;
        *(float2*)&Co[(tq + wrow + g) * Dn + hc + j * 8 + 2 * c] = o01;
        *(float2*)&Co[(tq + wrow + g + 8) * Dn + hc + j * 8 + 2 * c] = o23;
    }
}

// ---------------- add residual + layernorm, batched over 2 channels ----------------
__global__ void add_ln_kernel(const float* __restrict__ x, const float* __restrict__ r,
                              const float* __restrict__ g, const float* __restrict__ be,
                              float* __restrict__ out)
{
    long long row = blockIdx.x;
    const int chan = (row >= BSn) ? 1 : 0;
    const float* gp = g + chan * Dn;
    const float* bp = be + chan * Dn;
    const float* xp = x + row * Dn;
    const float* rp = r + row * Dn;
    int t = threadIdx.x;
    float v[4]; float s = 0.f, s2 = 0.f;
#pragma unroll
    for (int i = 0; i < 4; i++) {
        int cc = t + i * 128;
        v[i] = xp[cc] + rp[cc];
        s += v[i]; s2 += v[i] * v[i];
    }
    __shared__ float rs[128], rs2[128];
    rs[t] = s; rs2[t] = s2; __syncthreads();
#pragma unroll
    for (int o = 64; o > 0; o >>= 1) {
        if (t < o) { rs[t] += rs[t + o]; rs2[t] += rs2[t + o]; }
        __syncthreads();
    }
    float mean = rs[0] * (1.f / Dn);
    float var  = rs2[0] * (1.f / Dn) - mean * mean;
    float rstd = rsqrtf(var + 1e-5f);
    float* op = out + row * Dn;
#pragma unroll
    for (int i = 0; i < 4; i++) {
        int cc = t + i * 128;
        op[cc] = (v[i] - mean) * rstd * gp[cc] + bp[cc];
    }
}

// ---------------- pool + heads ----------------
__global__ void pool_kernel(const float* __restrict__ x, float* __restrict__ fused)
{
    int idx = blockIdx.x * 256 + threadIdx.x;
    int b = idx >> 10;
    int c = idx & 1023;
    const float* src = (c < Dn) ? (x + (long long)b * Sn * Dn + c)
                                : (x + RR + (long long)b * Sn * Dn + (c - Dn));
    float s = 0.f;
    for (int t = 0; t < Sn; t++) s += src[(long long)t * Dn];
    fused[idx] = s * (1.f / Sn);
}

__global__ void head_kernel(const float* __restrict__ fused,
                            const float* __restrict__ w1, const float* __restrict__ b1,
                            const float* __restrict__ w2, const float* __restrict__ b2,
                            float* __restrict__ out)
{
    __shared__ float sf[2 * Dn];
    int b = blockIdx.x, t = threadIdx.x;
    sf[t]      = fused[b * 2 * Dn + t];
    sf[t + Dn] = fused[b * 2 * Dn + t + Dn];
    __syncthreads();
    float h = b1[t];
    for (int k = 0; k < 2 * Dn; k++)
        h += sf[k] * w1[k * Dn + t];
    h = fmaxf(h, 0.f);
    __shared__ float r0[512], r1[512];
    r0[t] = h * w2[t * 2 + 0];
    r1[t] = h * w2[t * 2 + 1];
    __syncthreads();
#pragma unroll
    for (int o = 256; o > 0; o >>= 1) {
        if (t < o) { r0[t] += r0[t + o]; r1[t] += r1[t + o]; }
        __syncthreads();
    }
    if (t == 0) {
        out[b * 2 + 0] = r0[0] + b2[0];
        out[b * 2 + 1] = r1[0] + b2[1];
    }
}

extern "C" void kernel_launch(void* const* d_in, const int* in_sizes, int n_in,
                              void* d_out, int out_size)
{
    const float* left_wrist  = (const float*)d_in[0];
    const float* right_wrist = (const float*)d_in[1];
    const float* Wl = (const float*)d_in[2];
    const float* bl = (const float*)d_in[3];
    const float* Wr = (const float*)d_in[4];
    const float* br = (const float*)d_in[5];
    const float* pe = (const float*)d_in[6];
    const float* mha_w    = (const float*)d_in[7];
    const float* mha_b    = (const float*)d_in[8];
    const float* mha_ln_g = (const float*)d_in[9];
    const float* mha_ln_b = (const float*)d_in[10];
    const float* ff_w1    = (const float*)d_in[11];
    const float* ff_b1    = (const float*)d_in[12];
    const float* ff_w2    = (const float*)d_in[13];
    const float* ff_b2    = (const float*)d_in[14];
    const float* ff_ln_g  = (const float*)d_in[15];
    const float* ff_ln_b  = (const float*)d_in[16];
    const float* h1_w1 = (const float*)d_in[17];
    const float* h1_b1 = (const float*)d_in[18];
    const float* h1_w2 = (const float*)d_in[19];
    const float* h1_b2 = (const float*)d_in[20];
    const float* h2_w1 = (const float*)d_in[21];
    const float* h2_b1 = (const float*)d_in[22];
    const float* h2_w2 = (const float*)d_in[23];
    const float* h2_b2 = (const float*)d_in[24];
    float* out = (float*)d_out;

    float *pX, *pC, *pQKV, *pCtx, *pO, *pFfh, *pFused;
    cudaGetSymbolAddress((void**)&pX,    gbuf_x);
    cudaGetSymbolAddress((void**)&pC,    gbuf_c);
    cudaGetSymbolAddress((void**)&pQKV,  gbuf_qkv);
    cudaGetSymbolAddress((void**)&pCtx,  gbuf_ctx);
    cudaGetSymbolAddress((void**)&pO,    gbuf_o);
    cudaGetSymbolAddress((void**)&pFfh,  gbuf_ffh);
    cudaGetSymbolAddress((void**)&pFused, gbuf_fused);

    cudaFuncSetAttribute(flash_kernel, cudaFuncAttributeMaxDynamicSharedMemorySize, FA_SMEM_BYTES);

    embed_kernel<<<(BSn * Dn) / 256, 256>>>(left_wrist,  Wl, bl, pe, pX);
    embed_kernel<<<(BSn * Dn) / 256, 256>>>(right_wrist, Wr, br, pe, pX + RR);

    const dim3 gProj(Dn / BN, BSn / BM, 2);      // 4 x 32 x 2
    const dim3 gQKV(Dn / BN, BSn / BM, 6);       // 4 x 32 x 6
    const dim3 gFlash(Sn / 128, Bn * Hn, 2);     // 8 x 32 x 2
    const dim3 gFf1(Fn / BN, BSn / BM, 2);       // 16 x 32 x 2

    for (int l = 0; l < Ln; l++) {
        const float* w_base  = mha_w    + (long long)l * 4 * 4 * Dn * Dn;
        const float* b_base  = mha_b    + (long long)l * 4 * 4 * Dn;
        const float* lg_base = mha_ln_g + (long long)l * 4 * Dn;
        const float* lb_base = mha_ln_b + (long long)l * 4 * Dn;

        // ---- cross attention (blocks 0,1) ----
        tgemm<false><<<gQKV, 256>>>(pX, w_base, b_base, pQKV,
            Dn, Dn, Dn, Dn, 3,
            0, RR, RR, 0,
            4LL * Dn * Dn, (long long)Dn * Dn, 4LL * Dn, (long long)Dn, RR);
        flash_kernel<<<gFlash, 256, FA_SMEM_BYTES>>>(pQKV, pCtx);
        tgemm<false><<<gProj, 256>>>(pCtx, w_base + 3LL * Dn * Dn, b_base + 3LL * Dn, pO,
            Dn, Dn, Dn, Dn, 1,
            0, 0, RR, 0,
            4LL * Dn * Dn, 0, 4LL * Dn, 0, RR);
        add_ln_kernel<<<2 * BSn, 128>>>(pO, pX, lg_base, lb_base, pC);

        // ---- self attention (blocks 2,3) ----
        tgemm<false><<<gQKV, 256>>>(pC, w_base + 2LL * 4 * Dn * Dn, b_base + 2LL * 4 * Dn, pQKV,
            Dn, Dn, Dn, Dn, 3,
            0, 0, RR, RR,
            4LL * Dn * Dn, (long long)Dn * Dn, 4LL * Dn, (long long)Dn, RR);
        flash_kernel<<<gFlash, 256, FA_SMEM_BYTES>>>(pQKV, pCtx);
        tgemm<false><<<gProj, 256>>>(pCtx, w_base + (2LL * 4 + 3) * Dn * Dn, b_base + (2LL * 4 + 3) * Dn, pO,
            Dn, Dn, Dn, Dn, 1,
            0, 0, RR, 0,
            4LL * Dn * Dn, 0, 4LL * Dn, 0, RR);
        add_ln_kernel<<<2 * BSn, 128>>>(pO, pC, lg_base + 2 * Dn, lb_base + 2 * Dn, pX);

        // ---- FFNs ----
        tgemm<true><<<gFf1, 256>>>(pX, ff_w1 + (long long)l * 2 * Dn * Fn, ff_b1 + (long long)l * 2 * Fn, pFfh,
            Dn, Dn, Fn, Fn, 1,
            0, 0, RR, 0,
            (long long)Dn * Fn, 0, (long long)Fn, 0, (long long)BSn * Fn);
        tgemm<false><<<gProj, 256>>>(pFfh, ff_w2 + (long long)l * 2 * Fn * Dn, ff_b2 + (long long)l * 2 * Dn, pO,
            Fn, Fn, Dn, Dn, 1,
            0, 0, (long long)BSn * Fn, 0,
            (long long)Fn * Dn, 0, (long long)Dn, 0, RR);
        add_ln_kernel<<<2 * BSn, 128>>>(pO, pX, ff_ln_g + (long long)l * 2 * Dn, ff_ln_b + (long long)l * 2 * Dn, pX);
    }

    pool_kernel<<<(Bn * 2 * Dn) / 256, 256>>>(pX, pFused);
    head_kernel<<<Bn, 512>>>(pFused, h1_w1, h1_b1, h1_w2, h1_b2, out);
    head_kernel<<<Bn, 512>>>(pFused, h2_w1, h2_b1, h2_w2, h2_b2, out + Bn * 2);
}